// round 1
// baseline (speedup 1.0000x reference)
#include <cuda_runtime.h>

// Problem constants
#define Bsz   64
#define Tlen  256
#define INSZ  256
#define Hdim  64
#define Gdim  256        // 4*Hdim
#define Vocab 8000
#define Mrows (Bsz * Tlen)   // 16384

// Scratch (device globals; no allocation allowed in kernel_launch)
__device__ float g_xproj[Mrows * Gdim];   // 16 MB, reused for layer 1 projection
__device__ float g_h1[Mrows * Hdim];      // 4 MB
__device__ float g_h2[Mrows * Hdim];      // 4 MB

// ---------------- packed f32x2 helpers (exact fp32, 2x FMA-pipe throughput) ----------
__device__ __forceinline__ unsigned long long pack2(float x) {
    unsigned long long r;
    asm("mov.b64 %0, {%1, %1};" : "=l"(r) : "f"(x));
    return r;
}
__device__ __forceinline__ void fma2(unsigned long long& d, unsigned long long a,
                                     unsigned long long b) {
    asm("fma.rn.f32x2 %0, %1, %2, %0;" : "+l"(d) : "l"(a), "l"(b));
}
__device__ __forceinline__ float2 unpack2(unsigned long long v) {
    float2 f;
    asm("mov.b64 {%0, %1}, %2;" : "=f"(f.x), "=f"(f.y) : "l"(v));
    return f;
}

// ---------------- generic C[M,N] = A[M,K] * B[N,K]^T + bias1 (+bias2) ----------------
// Requirements: M % 64 == 0, N % 64 == 0, K % 16 == 0. 256 threads, 64x64 block tile,
// 4x4 per-thread micro-tile, packed f32x2 accumulation.
__global__ void gemm_nt_bias(const float* __restrict__ A, const float* __restrict__ Bm,
                             const float* __restrict__ bias1, const float* __restrict__ bias2,
                             float* __restrict__ C, int M, int N, int K)
{
    __shared__ __align__(16) float As[64][17];   // [m][k], pad to kill bank conflicts
    __shared__ __align__(16) float Bs[16][68];   // [k][n] (transposed on store)

    const int t  = threadIdx.x;
    const int bm = blockIdx.y * 64;
    const int bn = blockIdx.x * 64;
    const int tm = (t >> 4) << 2;   // 4*(t/16): micro-tile row base
    const int tn = (t & 15) << 2;   // 4*(t%16): micro-tile col base
    const int lr = t >> 2;          // load row 0..63
    const int lk = (t & 3) << 2;    // load k-offset {0,4,8,12}

    unsigned long long acc[4][2];
#pragma unroll
    for (int i = 0; i < 4; i++) { acc[i][0] = 0ULL; acc[i][1] = 0ULL; }

    const float* Aptr = A  + (size_t)(bm + lr) * K + lk;
    const float* Bptr = Bm + (size_t)(bn + lr) * K + lk;

    for (int k0 = 0; k0 < K; k0 += 16) {
        float4 av = *reinterpret_cast<const float4*>(Aptr + k0);
        float4 bv = *reinterpret_cast<const float4*>(Bptr + k0);
        As[lr][lk + 0] = av.x; As[lr][lk + 1] = av.y;
        As[lr][lk + 2] = av.z; As[lr][lk + 3] = av.w;
        Bs[lk + 0][lr] = bv.x; Bs[lk + 1][lr] = bv.y;
        Bs[lk + 2][lr] = bv.z; Bs[lk + 3][lr] = bv.w;
        __syncthreads();
#pragma unroll
        for (int kk = 0; kk < 16; kk++) {
            unsigned long long b0 =
                *reinterpret_cast<const unsigned long long*>(&Bs[kk][tn]);
            unsigned long long b1 =
                *reinterpret_cast<const unsigned long long*>(&Bs[kk][tn + 2]);
#pragma unroll
            for (int i = 0; i < 4; i++) {
                unsigned long long ap = pack2(As[tm + i][kk]);
                fma2(acc[i][0], ap, b0);
                fma2(acc[i][1], ap, b1);
            }
        }
        __syncthreads();
    }

    float4 bvec;
    bvec.x = bias1[bn + tn + 0];
    bvec.y = bias1[bn + tn + 1];
    bvec.z = bias1[bn + tn + 2];
    bvec.w = bias1[bn + tn + 3];
    if (bias2) {
        bvec.x += bias2[bn + tn + 0];
        bvec.y += bias2[bn + tn + 1];
        bvec.z += bias2[bn + tn + 2];
        bvec.w += bias2[bn + tn + 3];
    }
#pragma unroll
    for (int i = 0; i < 4; i++) {
        float2 lo = unpack2(acc[i][0]);
        float2 hi = unpack2(acc[i][1]);
        float4 v = make_float4(lo.x + bvec.x, lo.y + bvec.y,
                               hi.x + bvec.z, hi.y + bvec.w);
        *reinterpret_cast<float4*>(&C[(size_t)(bm + tm + i) * N + bn + tn]) = v;
    }
}

// ---------------- LSTM recurrence: one CTA per batch row, one thread per gate ---------
__device__ __forceinline__ float sigmoidf_(float x) {
    return 1.0f / (1.0f + __expf(-x));
}

__global__ void lstm_layer(const float* __restrict__ xproj,  // [B, T, 4H] incl. biases
                           const float* __restrict__ Whh,    // [4H, H]
                           float* __restrict__ hout)         // [B, T, H]
{
    __shared__ __align__(16) float h_sh[Hdim];
    __shared__ float gate_sh[Gdim];

    const int b = blockIdx.x;
    const int g = threadIdx.x;   // 0..255: gate output index (i|f|g|o blocks of 64)

    // W_hh row for this gate lives in registers (64 floats).
    float w[Hdim];
#pragma unroll
    for (int k = 0; k < Hdim; k++) w[k] = Whh[g * Hdim + k];

    float c = 0.0f;
    if (g < Hdim) h_sh[g] = 0.0f;
    __syncthreads();

    const float* xp = xproj + (size_t)b * Tlen * Gdim;
    float xcur = xp[g];   // prefetched input projection for t=0

    for (int t = 0; t < Tlen; t++) {
        float a0 = xcur, a1 = 0.0f, a2 = 0.0f, a3 = 0.0f;
        if (t + 1 < Tlen) xcur = xp[(size_t)(t + 1) * Gdim + g];  // prefetch next step
#pragma unroll
        for (int k = 0; k < Hdim; k += 4) {
            float4 h4 = *reinterpret_cast<const float4*>(&h_sh[k]);
            a0 = fmaf(w[k + 0], h4.x, a0);
            a1 = fmaf(w[k + 1], h4.y, a1);
            a2 = fmaf(w[k + 2], h4.z, a2);
            a3 = fmaf(w[k + 3], h4.w, a3);
        }
        gate_sh[g] = (a0 + a1) + (a2 + a3);
        __syncthreads();   // gates visible; also: all h_sh reads done before overwrite
        if (g < Hdim) {
            float iv = sigmoidf_(gate_sh[g]);
            float fv = sigmoidf_(gate_sh[g + Hdim]);
            float gv = tanhf(gate_sh[g + 2 * Hdim]);
            float ov = sigmoidf_(gate_sh[g + 3 * Hdim]);
            c = fv * c + iv * gv;
            float hn = ov * tanhf(c);
            h_sh[g] = hn;
            hout[((size_t)b * Tlen + t) * Hdim + g] = hn;
        }
        __syncthreads();   // h_sh update visible for next step
    }
}

// ------------------------------------ launch --------------------------------------
extern "C" void kernel_launch(void* const* d_in, const int* in_sizes, int n_in,
                              void* d_out, int out_size)
{
    (void)in_sizes; (void)n_in; (void)out_size;
    const float* x     = (const float*)d_in[0];   // [B,T,256]
    const float* W_ih0 = (const float*)d_in[1];   // [256,256]
    const float* W_hh0 = (const float*)d_in[2];   // [256,64]
    const float* b_ih0 = (const float*)d_in[3];   // [256]
    const float* b_hh0 = (const float*)d_in[4];   // [256]
    const float* W_ih1 = (const float*)d_in[5];   // [256,64]
    const float* W_hh1 = (const float*)d_in[6];   // [256,64]
    const float* b_ih1 = (const float*)d_in[7];   // [256]
    const float* b_hh1 = (const float*)d_in[8];   // [256]
    const float* Wl    = (const float*)d_in[9];   // [8000,64]
    const float* bl    = (const float*)d_in[10];  // [8000]
    float* out = (float*)d_out;                   // [B,T,8000]

    void* p;
    cudaGetSymbolAddress(&p, g_xproj); float* xproj = (float*)p;
    cudaGetSymbolAddress(&p, g_h1);    float* h1    = (float*)p;
    cudaGetSymbolAddress(&p, g_h2);    float* h2    = (float*)p;

    // Layer 0 input projection: [16384,256] x [256,256]^T (+ b_ih0 + b_hh0)
    gemm_nt_bias<<<dim3(Gdim / 64, Mrows / 64), 256>>>(
        x, W_ih0, b_ih0, b_hh0, xproj, Mrows, Gdim, INSZ);

    // Layer 0 recurrence
    lstm_layer<<<Bsz, Gdim>>>(xproj, W_hh0, h1);

    // Layer 1 input projection: [16384,64] x [256,64]^T (+ b_ih1 + b_hh1)
    gemm_nt_bias<<<dim3(Gdim / 64, Mrows / 64), 256>>>(
        h1, W_ih1, b_ih1, b_hh1, xproj, Mrows, Gdim, Hdim);

    // Layer 1 recurrence
    lstm_layer<<<Bsz, Gdim>>>(xproj, W_hh1, h2);

    // Logits: [16384,64] x [8000,64]^T + bl
    gemm_nt_bias<<<dim3(Vocab / 64, Mrows / 64), 256>>>(
        h2, Wl, bl, nullptr, out, Mrows, Vocab, Hdim);
}

// round 3
// speedup vs baseline: 1.4779x; 1.4779x over previous
#include <cuda_runtime.h>
#include <cuda_bf16.h>
#include <cstdint>

// Problem constants
#define Bsz   64
#define Tlen  256
#define INSZ  256
#define Hdim  64
#define Gdim  256        // 4*Hdim
#define Vocab 8000
#define Mrows (Bsz * Tlen)   // 16384

// Scratch (device globals; no allocation allowed in kernel_launch)
__device__ float g_xproj[Mrows * Gdim];   // 16 MB, reused for layer 1 projection
__device__ float g_h1[Mrows * Hdim];      // 4 MB
__device__ __nv_bfloat16 g_Ahi[Mrows * Hdim];
__device__ __nv_bfloat16 g_Alo[Mrows * Hdim];
__device__ __nv_bfloat16 g_Bhi[Vocab * Hdim];
__device__ __nv_bfloat16 g_Blo[Vocab * Hdim];

// ---------------- packed f32x2 helpers (exact fp32, 2x FMA-pipe throughput) ----------
__device__ __forceinline__ unsigned long long pack2(float x) {
    unsigned long long r;
    asm("mov.b64 %0, {%1, %1};" : "=l"(r) : "f"(x));
    return r;
}
__device__ __forceinline__ unsigned long long pack2v(float x, float y) {
    unsigned long long r;
    asm("mov.b64 %0, {%1, %2};" : "=l"(r) : "f"(x), "f"(y));
    return r;
}
__device__ __forceinline__ void fma2(unsigned long long& d, unsigned long long a,
                                     unsigned long long b) {
    asm("fma.rn.f32x2 %0, %1, %2, %0;" : "+l"(d) : "l"(a), "l"(b));
}
__device__ __forceinline__ float2 unpack2(unsigned long long v) {
    float2 f;
    asm("mov.b64 {%0, %1}, %2;" : "=f"(f.x), "=f"(f.y) : "l"(v));
    return f;
}
__device__ __forceinline__ float fast_rcp(float x) {
    float r;
    asm("rcp.approx.f32 %0, %1;" : "=f"(r) : "f"(x));
    return r;
}
__device__ __forceinline__ float sigmoidf_(float x) {
    return fast_rcp(1.0f + __expf(-x));
}
__device__ __forceinline__ float tanh_fast(float x) {
    // tanh(x) = 1 - 2/(1+e^{2x})
    return 1.0f - 2.0f * fast_rcp(1.0f + __expf(2.0f * x));
}

// ---------------- generic C[M,N] = A[M,K] * B[N,K]^T + bias1 (+bias2) ----------------
__global__ void gemm_nt_bias(const float* __restrict__ A, const float* __restrict__ Bm,
                             const float* __restrict__ bias1, const float* __restrict__ bias2,
                             float* __restrict__ C, int M, int N, int K)
{
    __shared__ __align__(16) float As[64][17];
    __shared__ __align__(16) float Bs[16][68];

    const int t  = threadIdx.x;
    const int bm = blockIdx.y * 64;
    const int bn = blockIdx.x * 64;
    const int tm = (t >> 4) << 2;
    const int tn = (t & 15) << 2;
    const int lr = t >> 2;
    const int lk = (t & 3) << 2;

    unsigned long long acc[4][2];
#pragma unroll
    for (int i = 0; i < 4; i++) { acc[i][0] = 0ULL; acc[i][1] = 0ULL; }

    const float* Aptr = A  + (size_t)(bm + lr) * K + lk;
    const float* Bptr = Bm + (size_t)(bn + lr) * K + lk;

    for (int k0 = 0; k0 < K; k0 += 16) {
        float4 av = *reinterpret_cast<const float4*>(Aptr + k0);
        float4 bv = *reinterpret_cast<const float4*>(Bptr + k0);
        As[lr][lk + 0] = av.x; As[lr][lk + 1] = av.y;
        As[lr][lk + 2] = av.z; As[lr][lk + 3] = av.w;
        Bs[lk + 0][lr] = bv.x; Bs[lk + 1][lr] = bv.y;
        Bs[lk + 2][lr] = bv.z; Bs[lk + 3][lr] = bv.w;
        __syncthreads();
#pragma unroll
        for (int kk = 0; kk < 16; kk++) {
            unsigned long long b0 =
                *reinterpret_cast<const unsigned long long*>(&Bs[kk][tn]);
            unsigned long long b1 =
                *reinterpret_cast<const unsigned long long*>(&Bs[kk][tn + 2]);
#pragma unroll
            for (int i = 0; i < 4; i++) {
                unsigned long long ap = pack2(As[tm + i][kk]);
                fma2(acc[i][0], ap, b0);
                fma2(acc[i][1], ap, b1);
            }
        }
        __syncthreads();
    }

    float4 bvec;
    bvec.x = bias1[bn + tn + 0];
    bvec.y = bias1[bn + tn + 1];
    bvec.z = bias1[bn + tn + 2];
    bvec.w = bias1[bn + tn + 3];
    if (bias2) {
        bvec.x += bias2[bn + tn + 0];
        bvec.y += bias2[bn + tn + 1];
        bvec.z += bias2[bn + tn + 2];
        bvec.w += bias2[bn + tn + 3];
    }
#pragma unroll
    for (int i = 0; i < 4; i++) {
        float2 lo = unpack2(acc[i][0]);
        float2 hi = unpack2(acc[i][1]);
        float4 v = make_float4(lo.x + bvec.x, lo.y + bvec.y,
                               hi.x + bvec.z, hi.y + bvec.w);
        *reinterpret_cast<float4*>(&C[(size_t)(bm + tm + i) * N + bn + tn]) = v;
    }
}

// ---------------- LSTM recurrence: one CTA per batch row, one thread per gate ---------
// f32x2 matvec + parallel gate activation; only c/h update is serial per step.
// If hi/lo are non-null, output is written as a bf16 split instead of fp32.
__global__ void lstm_layer(const float* __restrict__ xproj,  // [B, T, 4H] incl. biases
                           const float* __restrict__ Whh,    // [4H, H]
                           float* __restrict__ hout,         // [B, T, H] or null
                           __nv_bfloat16* __restrict__ hi_out,
                           __nv_bfloat16* __restrict__ lo_out)
{
    __shared__ __align__(16) float h_sh[Hdim];
    __shared__ float gate_sh[Gdim];

    const int b = blockIdx.x;
    const int g = threadIdx.x;       // 0..255
    const int blk = g >> 6;          // 0:i  1:f  2:g  3:o

    unsigned long long wp[Hdim / 2];
#pragma unroll
    for (int j = 0; j < Hdim / 2; j++) {
        float2 v = *reinterpret_cast<const float2*>(Whh + g * Hdim + 2 * j);
        wp[j] = pack2v(v.x, v.y);
    }

    float c = 0.0f;
    if (g < Hdim) h_sh[g] = 0.0f;
    __syncthreads();

    const float* xp = xproj + (size_t)b * Tlen * Gdim;
    float xcur = xp[g];

    const unsigned long long* hp =
        reinterpret_cast<const unsigned long long*>(h_sh);

    for (int t = 0; t < Tlen; t++) {
        unsigned long long a0 = 0ULL, a1 = 0ULL, a2 = 0ULL, a3 = 0ULL;
        float xnext = (t + 1 < Tlen) ? xp[(size_t)(t + 1) * Gdim + g] : 0.0f;
#pragma unroll
        for (int j = 0; j < Hdim / 2; j += 4) {
            fma2(a0, wp[j + 0], hp[j + 0]);
            fma2(a1, wp[j + 1], hp[j + 1]);
            fma2(a2, wp[j + 2], hp[j + 2]);
            fma2(a3, wp[j + 3], hp[j + 3]);
        }
        float2 s0 = unpack2(a0), s1 = unpack2(a1), s2 = unpack2(a2), s3 = unpack2(a3);
        float val = xcur + (((s0.x + s0.y) + (s1.x + s1.y)) +
                            ((s2.x + s2.y) + (s3.x + s3.y)));
        xcur = xnext;

        float act = (blk == 2) ? tanh_fast(val) : sigmoidf_(val);
        gate_sh[g] = act;
        __syncthreads();

        if (g < Hdim) {
            float iv = gate_sh[g];
            float fv = gate_sh[g + Hdim];
            float gv = gate_sh[g + 2 * Hdim];
            float ov = gate_sh[g + 3 * Hdim];
            c = fv * c + iv * gv;
            float hn = ov * tanh_fast(c);
            h_sh[g] = hn;
            size_t idx = ((size_t)b * Tlen + t) * Hdim + g;
            if (hout) hout[idx] = hn;
            if (hi_out) {
                __nv_bfloat16 h = __float2bfloat16(hn);
                hi_out[idx] = h;
                lo_out[idx] = __float2bfloat16(hn - __bfloat162float(h));
            }
        }
        __syncthreads();
    }
}

// ---------------- bf16 split conversion:  x = hi + lo  (both bf16) ------------------
__global__ void cvt_split(const float* __restrict__ in, __nv_bfloat16* __restrict__ hi,
                          __nv_bfloat16* __restrict__ lo, int n)
{
    int i = blockIdx.x * blockDim.x + threadIdx.x;
    if (i < n) {
        float v = in[i];
        __nv_bfloat16 h = __float2bfloat16(v);
        float hf = __bfloat162float(h);
        hi[i] = h;
        lo[i] = __float2bfloat16(v - hf);
    }
}

// ---------------- HMMA logits GEMM:  C[16384,8000] = A[.,64] * B[8000,64]^T + bl -----
// CTA tile 128x64, K=64 (single SMEM stage). 8 warps: 4 (m) x 2 (n), warp tile 32x32.
// 3-pass bf16 split accumulated in fp32 registers: AhiBhi + AhiBlo + AloBhi.
#define SWZ128(off) ((off) ^ (((off) >> 3) & 0x70))
#define LGA_HI 0
#define LGA_LO (128 * 128)           // 16384
#define LGB_HI (2 * 128 * 128)       // 32768
#define LGB_LO (2 * 128 * 128 + 64 * 128)   // 40960
#define LG_SMEM (49152 + 1024)

static __device__ __forceinline__ uint32_t smem_u32(const void* p) {
    uint32_t a;
    asm("{ .reg .u64 t; cvta.to.shared.u64 t, %1; cvt.u32.u64 %0, t; }"
        : "=r"(a) : "l"(p));
    return a;
}
__device__ __forceinline__ void ldsm_x4(uint32_t& r0, uint32_t& r1, uint32_t& r2,
                                        uint32_t& r3, uint32_t addr) {
    asm volatile("ldmatrix.sync.aligned.m8n8.x4.shared.b16 {%0,%1,%2,%3}, [%4];"
                 : "=r"(r0), "=r"(r1), "=r"(r2), "=r"(r3) : "r"(addr));
}
__device__ __forceinline__ void mma_bf16(float* c, uint32_t a0, uint32_t a1,
                                         uint32_t a2, uint32_t a3,
                                         uint32_t b0, uint32_t b1) {
    asm volatile("mma.sync.aligned.m16n8k16.row.col.f32.bf16.bf16.f32 "
                 "{%0,%1,%2,%3}, {%4,%5,%6,%7}, {%8,%9}, {%0,%1,%2,%3};"
                 : "+f"(c[0]), "+f"(c[1]), "+f"(c[2]), "+f"(c[3])
                 : "r"(a0), "r"(a1), "r"(a2), "r"(a3), "r"(b0), "r"(b1));
}

__global__ void __launch_bounds__(256)
logits_gemm(const __nv_bfloat16* __restrict__ Ahi, const __nv_bfloat16* __restrict__ Alo,
            const __nv_bfloat16* __restrict__ Bhi, const __nv_bfloat16* __restrict__ Blo,
            const float* __restrict__ bias, float* __restrict__ C)
{
    extern __shared__ char smem_raw[];
    const uint32_t sb0 = smem_u32(smem_raw);
    const uint32_t sb = (sb0 + 1023) & ~1023u;          // 1024-aligned SMEM base
    char* base = smem_raw + (sb - sb0);

    const int tid = threadIdx.x;
    const int lane = tid & 31;
    const int wid = tid >> 5;
    const int wm = wid & 3;        // warp m-tile (0..3), 32 rows each
    const int wn = wid >> 2;       // warp n-tile (0..1), 32 cols each
    const int bm = blockIdx.y * 128;
    const int bn = blockIdx.x * 64;

    // ---- load A tiles (128 rows x 128B): thread t -> row t/2, chunks (t&1)*4..+3 ----
    {
        const int row = tid >> 1;
        const int cb = (tid & 1) * 4;
        const uint4* sh = reinterpret_cast<const uint4*>(Ahi + (size_t)(bm + row) * Hdim);
        const uint4* sl = reinterpret_cast<const uint4*>(Alo + (size_t)(bm + row) * Hdim);
#pragma unroll
        for (int i = 0; i < 4; i++) {
            uint32_t off = SWZ128((uint32_t)(row * 128 + (cb + i) * 16));
            *reinterpret_cast<uint4*>(base + LGA_HI + off) = sh[cb + i];
            *reinterpret_cast<uint4*>(base + LGA_LO + off) = sl[cb + i];
        }
    }
    // ---- load B tiles (64 rows x 128B): thread t -> row t/4, chunks (t&3)*2, +1 ----
    {
        const int row = tid >> 2;
        const int cb = (tid & 3) * 2;
        const uint4* sh = reinterpret_cast<const uint4*>(Bhi + (size_t)(bn + row) * Hdim);
        const uint4* sl = reinterpret_cast<const uint4*>(Blo + (size_t)(bn + row) * Hdim);
#pragma unroll
        for (int i = 0; i < 2; i++) {
            uint32_t off = SWZ128((uint32_t)(row * 128 + (cb + i) * 16));
            *reinterpret_cast<uint4*>(base + LGB_HI + off) = sh[cb + i];
            *reinterpret_cast<uint4*>(base + LGB_LO + off) = sl[cb + i];
        }
    }
    __syncthreads();

    float acc[2][4][4];   // [mt][nt][frag]
#pragma unroll
    for (int i = 0; i < 2; i++)
#pragma unroll
        for (int j = 0; j < 4; j++)
#pragma unroll
            for (int q = 0; q < 4; q++) acc[i][j][q] = 0.0f;

    const uint32_t aBase[3] = { sb + LGA_HI, sb + LGA_HI, sb + LGA_LO };
    const uint32_t bBase[3] = { sb + LGB_HI, sb + LGB_LO, sb + LGB_HI };

    const int rsel = lane & 15;      // row within 16-row ldmatrix footprint
    const int csel = lane >> 4;      // extra 16B column

#pragma unroll
    for (int p = 0; p < 3; p++) {
        const uint32_t aB = aBase[p];
        const uint32_t bB = bBase[p];
#pragma unroll
        for (int ks = 0; ks < 4; ks++) {
            const int col16 = ks * 2 + csel;
            // A fragments: 2 m-tiles of 16
            uint32_t a[2][4];
#pragma unroll
            for (int mt = 0; mt < 2; mt++) {
                int row = wm * 32 + mt * 16 + rsel;
                uint32_t addr = aB + SWZ128((uint32_t)(row * 128 + col16 * 16));
                ldsm_x4(a[mt][0], a[mt][1], a[mt][2], a[mt][3], addr);
            }
            // B fragments: 2 ldmatrix.x4, each covers two 8-wide n-tiles
            uint32_t b0[4], b1[4];   // b0/b1 per n-tile 0..3
#pragma unroll
            for (int np = 0; np < 2; np++) {
                int row = wn * 32 + np * 16 + rsel;
                uint32_t addr = bB + SWZ128((uint32_t)(row * 128 + col16 * 16));
                uint32_t r0, r1, r2, r3;
                ldsm_x4(r0, r1, r2, r3, addr);
                b0[np * 2 + 0] = r0; b0[np * 2 + 1] = r1;
                b1[np * 2 + 0] = r2; b1[np * 2 + 1] = r3;
            }
#pragma unroll
            for (int mt = 0; mt < 2; mt++)
#pragma unroll
                for (int nt = 0; nt < 4; nt++)
                    mma_bf16(acc[mt][nt], a[mt][0], a[mt][1], a[mt][2], a[mt][3],
                             b0[nt], b1[nt]);
        }
    }

    // ---- epilogue: direct register -> GMEM (full 32B sectors per 4-lane group) ----
    const int gid = lane >> 2;
    const int tig = lane & 3;
#pragma unroll
    for (int nt = 0; nt < 4; nt++) {
        const int gn = bn + wn * 32 + nt * 8 + 2 * tig;
        float2 bv = *reinterpret_cast<const float2*>(bias + gn);
#pragma unroll
        for (int mt = 0; mt < 2; mt++) {
            const int gm0 = bm + wm * 32 + mt * 16 + gid;
            float2 v0 = make_float2(acc[mt][nt][0] + bv.x, acc[mt][nt][1] + bv.y);
            float2 v1 = make_float2(acc[mt][nt][2] + bv.x, acc[mt][nt][3] + bv.y);
            *reinterpret_cast<float2*>(C + (size_t)gm0 * Vocab + gn) = v0;
            *reinterpret_cast<float2*>(C + (size_t)(gm0 + 8) * Vocab + gn) = v1;
        }
    }
}

// ------------------------------------ launch --------------------------------------
extern "C" void kernel_launch(void* const* d_in, const int* in_sizes, int n_in,
                              void* d_out, int out_size)
{
    (void)in_sizes; (void)n_in; (void)out_size;
    const float* x     = (const float*)d_in[0];
    const float* W_ih0 = (const float*)d_in[1];
    const float* W_hh0 = (const float*)d_in[2];
    const float* b_ih0 = (const float*)d_in[3];
    const float* b_hh0 = (const float*)d_in[4];
    const float* W_ih1 = (const float*)d_in[5];
    const float* W_hh1 = (const float*)d_in[6];
    const float* b_ih1 = (const float*)d_in[7];
    const float* b_hh1 = (const float*)d_in[8];
    const float* Wl    = (const float*)d_in[9];
    const float* bl    = (const float*)d_in[10];
    float* out = (float*)d_out;

    void* p;
    cudaGetSymbolAddress(&p, g_xproj); float* xproj = (float*)p;
    cudaGetSymbolAddress(&p, g_h1);    float* h1    = (float*)p;
    cudaGetSymbolAddress(&p, g_Ahi);   __nv_bfloat16* Ahi = (__nv_bfloat16*)p;
    cudaGetSymbolAddress(&p, g_Alo);   __nv_bfloat16* Alo = (__nv_bfloat16*)p;
    cudaGetSymbolAddress(&p, g_Bhi);   __nv_bfloat16* Bhi = (__nv_bfloat16*)p;
    cudaGetSymbolAddress(&p, g_Blo);   __nv_bfloat16* Blo = (__nv_bfloat16*)p;

    // Wl split (independent of LSTM chain)
    cvt_split<<<(Vocab * Hdim + 255) / 256, 256>>>(Wl, Bhi, Blo, Vocab * Hdim);

    // Layer 0 input projection
    gemm_nt_bias<<<dim3(Gdim / 64, Mrows / 64), 256>>>(
        x, W_ih0, b_ih0, b_hh0, xproj, Mrows, Gdim, INSZ);
    // Layer 0 recurrence -> h1 (fp32)
    lstm_layer<<<Bsz, Gdim>>>(xproj, W_hh0, h1, nullptr, nullptr);
    // Layer 1 input projection
    gemm_nt_bias<<<dim3(Gdim / 64, Mrows / 64), 256>>>(
        h1, W_ih1, b_ih1, b_hh1, xproj, Mrows, Gdim, Hdim);
    // Layer 1 recurrence -> bf16 hi/lo split directly
    lstm_layer<<<Bsz, Gdim>>>(xproj, W_hh1, nullptr, Ahi, Alo);

    // Logits via HMMA bf16 3-pass split
    cudaFuncSetAttribute(logits_gemm, cudaFuncAttributeMaxDynamicSharedMemorySize, LG_SMEM);
    logits_gemm<<<dim3(Vocab / 64, Mrows / 128), 256, LG_SMEM>>>(
        Ahi, Alo, Bhi, Blo, bl, out);
}

// round 4
// speedup vs baseline: 1.4807x; 1.0019x over previous
#include <cuda_runtime.h>
#include <cuda_bf16.h>
#include <cstdint>

// Problem constants
#define Bsz   64
#define Tlen  256
#define INSZ  256
#define Hdim  64
#define Gdim  256        // 4*Hdim
#define Vocab 8000
#define Mrows (Bsz * Tlen)   // 16384

// Scratch (device globals; no allocation allowed in kernel_launch)
__device__ float g_xproj[Mrows * Gdim];
__device__ float g_h1[Mrows * Hdim];
__device__ __nv_bfloat16 g_Ahi[Mrows * Hdim];
__device__ __nv_bfloat16 g_Alo[Mrows * Hdim];
__device__ __nv_bfloat16 g_Bhi[Vocab * Hdim];
__device__ __nv_bfloat16 g_Blo[Vocab * Hdim];

// ---------------- packed f32x2 helpers ----------------
__device__ __forceinline__ unsigned long long pack2(float x) {
    unsigned long long r;
    asm("mov.b64 %0, {%1, %1};" : "=l"(r) : "f"(x));
    return r;
}
__device__ __forceinline__ unsigned long long pack2v(float x, float y) {
    unsigned long long r;
    asm("mov.b64 %0, {%1, %2};" : "=l"(r) : "f"(x), "f"(y));
    return r;
}
__device__ __forceinline__ void fma2(unsigned long long& d, unsigned long long a,
                                     unsigned long long b) {
    asm("fma.rn.f32x2 %0, %1, %2, %0;" : "+l"(d) : "l"(a), "l"(b));
}
__device__ __forceinline__ float2 unpack2(unsigned long long v) {
    float2 f;
    asm("mov.b64 {%0, %1}, %2;" : "=f"(f.x), "=f"(f.y) : "l"(v));
    return f;
}
__device__ __forceinline__ float fast_rcp(float x) {
    float r;
    asm("rcp.approx.f32 %0, %1;" : "=f"(r) : "f"(x));
    return r;
}
__device__ __forceinline__ float sigmoidf_(float x) {
    return fast_rcp(1.0f + __expf(-x));
}
__device__ __forceinline__ float tanh_fast(float x) {
    return 1.0f - 2.0f * fast_rcp(1.0f + __expf(2.0f * x));
}

// ---------------- generic C[M,N] = A[M,K] * B[N,K]^T + bias1 (+bias2) ----------------
__global__ void gemm_nt_bias(const float* __restrict__ A, const float* __restrict__ Bm,
                             const float* __restrict__ bias1, const float* __restrict__ bias2,
                             float* __restrict__ C, int M, int N, int K)
{
    __shared__ __align__(16) float As[64][17];
    __shared__ __align__(16) float Bs[16][68];

    const int t  = threadIdx.x;
    const int bm = blockIdx.y * 64;
    const int bn = blockIdx.x * 64;
    const int tm = (t >> 4) << 2;
    const int tn = (t & 15) << 2;
    const int lr = t >> 2;
    const int lk = (t & 3) << 2;

    unsigned long long acc[4][2];
#pragma unroll
    for (int i = 0; i < 4; i++) { acc[i][0] = 0ULL; acc[i][1] = 0ULL; }

    const float* Aptr = A  + (size_t)(bm + lr) * K + lk;
    const float* Bptr = Bm + (size_t)(bn + lr) * K + lk;

    for (int k0 = 0; k0 < K; k0 += 16) {
        float4 av = *reinterpret_cast<const float4*>(Aptr + k0);
        float4 bv = *reinterpret_cast<const float4*>(Bptr + k0);
        As[lr][lk + 0] = av.x; As[lr][lk + 1] = av.y;
        As[lr][lk + 2] = av.z; As[lr][lk + 3] = av.w;
        Bs[lk + 0][lr] = bv.x; Bs[lk + 1][lr] = bv.y;
        Bs[lk + 2][lr] = bv.z; Bs[lk + 3][lr] = bv.w;
        __syncthreads();
#pragma unroll
        for (int kk = 0; kk < 16; kk++) {
            unsigned long long b0 =
                *reinterpret_cast<const unsigned long long*>(&Bs[kk][tn]);
            unsigned long long b1 =
                *reinterpret_cast<const unsigned long long*>(&Bs[kk][tn + 2]);
#pragma unroll
            for (int i = 0; i < 4; i++) {
                unsigned long long ap = pack2(As[tm + i][kk]);
                fma2(acc[i][0], ap, b0);
                fma2(acc[i][1], ap, b1);
            }
        }
        __syncthreads();
    }

    float4 bvec;
    bvec.x = bias1[bn + tn + 0];
    bvec.y = bias1[bn + tn + 1];
    bvec.z = bias1[bn + tn + 2];
    bvec.w = bias1[bn + tn + 3];
    if (bias2) {
        bvec.x += bias2[bn + tn + 0];
        bvec.y += bias2[bn + tn + 1];
        bvec.z += bias2[bn + tn + 2];
        bvec.w += bias2[bn + tn + 3];
    }
#pragma unroll
    for (int i = 0; i < 4; i++) {
        float2 lo = unpack2(acc[i][0]);
        float2 hi = unpack2(acc[i][1]);
        float4 v = make_float4(lo.x + bvec.x, lo.y + bvec.y,
                               hi.x + bvec.z, hi.y + bvec.w);
        *reinterpret_cast<float4*>(&C[(size_t)(bm + tm + i) * N + bn + tn]) = v;
    }
}

// ---------------- LSTM recurrence (unchanged from passing R3) ---------
__global__ void lstm_layer(const float* __restrict__ xproj,
                           const float* __restrict__ Whh,
                           float* __restrict__ hout,
                           __nv_bfloat16* __restrict__ hi_out,
                           __nv_bfloat16* __restrict__ lo_out)
{
    __shared__ __align__(16) float h_sh[Hdim];
    __shared__ float gate_sh[Gdim];

    const int b = blockIdx.x;
    const int g = threadIdx.x;
    const int blk = g >> 6;

    unsigned long long wp[Hdim / 2];
#pragma unroll
    for (int j = 0; j < Hdim / 2; j++) {
        float2 v = *reinterpret_cast<const float2*>(Whh + g * Hdim + 2 * j);
        wp[j] = pack2v(v.x, v.y);
    }

    float c = 0.0f;
    if (g < Hdim) h_sh[g] = 0.0f;
    __syncthreads();

    const float* xp = xproj + (size_t)b * Tlen * Gdim;
    float xcur = xp[g];

    const unsigned long long* hp =
        reinterpret_cast<const unsigned long long*>(h_sh);

    for (int t = 0; t < Tlen; t++) {
        unsigned long long a0 = 0ULL, a1 = 0ULL, a2 = 0ULL, a3 = 0ULL;
        float xnext = (t + 1 < Tlen) ? xp[(size_t)(t + 1) * Gdim + g] : 0.0f;
#pragma unroll
        for (int j = 0; j < Hdim / 2; j += 4) {
            fma2(a0, wp[j + 0], hp[j + 0]);
            fma2(a1, wp[j + 1], hp[j + 1]);
            fma2(a2, wp[j + 2], hp[j + 2]);
            fma2(a3, wp[j + 3], hp[j + 3]);
        }
        float2 s0 = unpack2(a0), s1 = unpack2(a1), s2 = unpack2(a2), s3 = unpack2(a3);
        float val = xcur + (((s0.x + s0.y) + (s1.x + s1.y)) +
                            ((s2.x + s2.y) + (s3.x + s3.y)));
        xcur = xnext;

        float act = (blk == 2) ? tanh_fast(val) : sigmoidf_(val);
        gate_sh[g] = act;
        __syncthreads();

        if (g < Hdim) {
            float iv = gate_sh[g];
            float fv = gate_sh[g + Hdim];
            float gv = gate_sh[g + 2 * Hdim];
            float ov = gate_sh[g + 3 * Hdim];
            c = fv * c + iv * gv;
            float hn = ov * tanh_fast(c);
            h_sh[g] = hn;
            size_t idx = ((size_t)b * Tlen + t) * Hdim + g;
            if (hout) hout[idx] = hn;
            if (hi_out) {
                __nv_bfloat16 h = __float2bfloat16(hn);
                hi_out[idx] = h;
                lo_out[idx] = __float2bfloat16(hn - __bfloat162float(h));
            }
        }
        __syncthreads();
    }
}

// ---------------- bf16 split conversion ------------------
__global__ void cvt_split(const float* __restrict__ in, __nv_bfloat16* __restrict__ hi,
                          __nv_bfloat16* __restrict__ lo, int n)
{
    int i = blockIdx.x * blockDim.x + threadIdx.x;
    if (i < n) {
        float v = in[i];
        __nv_bfloat16 h = __float2bfloat16(v);
        float hf = __bfloat162float(h);
        hi[i] = h;
        lo[i] = __float2bfloat16(v - hf);
    }
}

// ============ HMMA logits GEMM, streaming/pipelined =============================
// Grid (125, 16): CTA owns one bn (64 vocab cols) and 8 m-tiles of 128 rows.
// B hi/lo resident in SMEM (16KB); A tiles double-buffered (2 x 32KB) via cp.async.
// 3-pass bf16 split per tile: AhiBhi + AhiBlo + AloBhi (identical math to R3 pass).
#define SWZ128(off) ((off) ^ (((off) >> 3) & 0x70))
#define LS_BHI  0
#define LS_BLO  8192
#define LS_A    16384
#define LS_ASTG 32768          // per-stage size (Ahi 16KB + Alo 16KB)
#define LS_ALO  16384          // lo offset within stage
#define LG_SMEM (16384 + 2 * 32768 + 1024)   // + alignment slack
#define NM_TILES 8

static __device__ __forceinline__ uint32_t smem_u32(const void* p) {
    uint32_t a;
    asm("{ .reg .u64 t; cvta.to.shared.u64 t, %1; cvt.u32.u64 %0, t; }"
        : "=r"(a) : "l"(p));
    return a;
}
__device__ __forceinline__ void cp16(uint32_t dst, const void* src) {
    asm volatile("cp.async.cg.shared.global [%0], [%1], 16;"
                 :: "r"(dst), "l"(src));
}
__device__ __forceinline__ void cp_commit() {
    asm volatile("cp.async.commit_group;" ::: "memory");
}
template <int N>
__device__ __forceinline__ void cp_wait() {
    asm volatile("cp.async.wait_group %0;" :: "n"(N) : "memory");
}
__device__ __forceinline__ void ldsm_x4(uint32_t& r0, uint32_t& r1, uint32_t& r2,
                                        uint32_t& r3, uint32_t addr) {
    asm volatile("ldmatrix.sync.aligned.m8n8.x4.shared.b16 {%0,%1,%2,%3}, [%4];"
                 : "=r"(r0), "=r"(r1), "=r"(r2), "=r"(r3) : "r"(addr));
}
__device__ __forceinline__ void mma_bf16(float* c, uint32_t a0, uint32_t a1,
                                         uint32_t a2, uint32_t a3,
                                         uint32_t b0, uint32_t b1) {
    asm volatile("mma.sync.aligned.m16n8k16.row.col.f32.bf16.bf16.f32 "
                 "{%0,%1,%2,%3}, {%4,%5,%6,%7}, {%8,%9}, {%0,%1,%2,%3};"
                 : "+f"(c[0]), "+f"(c[1]), "+f"(c[2]), "+f"(c[3])
                 : "r"(a0), "r"(a1), "r"(a2), "r"(a3), "r"(b0), "r"(b1));
}
__device__ __forceinline__ void stg_cs_f2(float* p, float x, float y) {
    asm volatile("st.global.cs.v2.f32 [%0], {%1,%2};" :: "l"(p), "f"(x), "f"(y));
}

// Issue cp.async for one A stage (hi+lo, 128 rows x 128B each)
__device__ __forceinline__ void load_A_stage(uint32_t sA, const __nv_bfloat16* Ahi,
                                             const __nv_bfloat16* Alo, int bm, int tid) {
    const int row = tid >> 1;
    const int cb = (tid & 1) * 4;
    const char* sh = reinterpret_cast<const char*>(Ahi + (size_t)(bm + row) * Hdim);
    const char* sl = reinterpret_cast<const char*>(Alo + (size_t)(bm + row) * Hdim);
#pragma unroll
    for (int i = 0; i < 4; i++) {
        uint32_t off = SWZ128((uint32_t)(row * 128 + (cb + i) * 16));
        cp16(sA + off, sh + (cb + i) * 16);
        cp16(sA + LS_ALO + off, sl + (cb + i) * 16);
    }
}

__global__ void __launch_bounds__(256)
logits_gemm(const __nv_bfloat16* __restrict__ Ahi, const __nv_bfloat16* __restrict__ Alo,
            const __nv_bfloat16* __restrict__ Bhi, const __nv_bfloat16* __restrict__ Blo,
            const float* __restrict__ bias, float* __restrict__ C)
{
    extern __shared__ char smem_raw[];
    const uint32_t sb0 = smem_u32(smem_raw);
    const uint32_t sb = (sb0 + 1023) & ~1023u;

    const int tid = threadIdx.x;
    const int lane = tid & 31;
    const int wid = tid >> 5;
    const int wm = wid & 3;        // warp m-tile (0..3)
    const int wn = wid >> 2;       // warp n-tile (0..1)
    const int bn = blockIdx.x * 64;
    const int bm0 = blockIdx.y * (NM_TILES * 128);

    // ---- resident B tiles (hi/lo), cp.async ----
    {
        const int row = tid >> 2;
        const int cb = (tid & 3) * 2;
        const char* sh = reinterpret_cast<const char*>(Bhi + (size_t)(bn + row) * Hdim);
        const char* sl = reinterpret_cast<const char*>(Blo + (size_t)(bn + row) * Hdim);
#pragma unroll
        for (int i = 0; i < 2; i++) {
            uint32_t off = SWZ128((uint32_t)(row * 128 + (cb + i) * 16));
            cp16(sb + LS_BHI + off, sh + (cb + i) * 16);
            cp16(sb + LS_BLO + off, sl + (cb + i) * 16);
        }
    }
    // ---- A stage 0 ----
    load_A_stage(sb + LS_A, Ahi, Alo, bm0, tid);
    cp_commit();   // group: B + A0

    // bias registers (bn fixed per CTA)
    const int gid = lane >> 2;
    const int tig = lane & 3;
    float2 bv[4];
#pragma unroll
    for (int nt = 0; nt < 4; nt++)
        bv[nt] = *reinterpret_cast<const float2*>(bias + bn + wn * 32 + nt * 8 + 2 * tig);

    const int rsel = lane & 15;
    const int csel = lane >> 4;

    for (int it = 0; it < NM_TILES; it++) {
        const uint32_t sA = sb + LS_A + (it & 1) * LS_ASTG;
        if (it + 1 < NM_TILES) {
            load_A_stage(sb + LS_A + ((it + 1) & 1) * LS_ASTG, Ahi, Alo,
                         bm0 + (it + 1) * 128, tid);
            cp_commit();
            cp_wait<1>();    // this tile's data ready; next stays in flight
        } else {
            cp_wait<0>();
        }
        __syncthreads();

        float acc[2][4][4];
#pragma unroll
        for (int i = 0; i < 2; i++)
#pragma unroll
            for (int j = 0; j < 4; j++)
#pragma unroll
                for (int q = 0; q < 4; q++) acc[i][j][q] = 0.0f;

        const uint32_t aBase[3] = { sA, sA, sA + LS_ALO };
        const uint32_t bBase[3] = { sb + LS_BHI, sb + LS_BLO, sb + LS_BHI };

#pragma unroll
        for (int p = 0; p < 3; p++) {
            const uint32_t aB = aBase[p];
            const uint32_t bB = bBase[p];
#pragma unroll
            for (int ks = 0; ks < 4; ks++) {
                const int col16 = ks * 2 + csel;
                uint32_t a[2][4];
#pragma unroll
                for (int mt = 0; mt < 2; mt++) {
                    int row = wm * 32 + mt * 16 + rsel;
                    uint32_t addr = aB + SWZ128((uint32_t)(row * 128 + col16 * 16));
                    ldsm_x4(a[mt][0], a[mt][1], a[mt][2], a[mt][3], addr);
                }
                uint32_t b0[4], b1[4];
#pragma unroll
                for (int np = 0; np < 2; np++) {
                    int row = wn * 32 + np * 16 + rsel;
                    uint32_t addr = bB + SWZ128((uint32_t)(row * 128 + col16 * 16));
                    uint32_t r0, r1, r2, r3;
                    ldsm_x4(r0, r1, r2, r3, addr);
                    b0[np * 2 + 0] = r0; b0[np * 2 + 1] = r1;
                    b1[np * 2 + 0] = r2; b1[np * 2 + 1] = r3;
                }
#pragma unroll
                for (int mt = 0; mt < 2; mt++)
#pragma unroll
                    for (int nt = 0; nt < 4; nt++)
                        mma_bf16(acc[mt][nt], a[mt][0], a[mt][1], a[mt][2], a[mt][3],
                                 b0[nt], b1[nt]);
            }
        }

        // epilogue: streaming stores (output never re-read)
        const int bm = bm0 + it * 128;
#pragma unroll
        for (int nt = 0; nt < 4; nt++) {
            const int gn = bn + wn * 32 + nt * 8 + 2 * tig;
#pragma unroll
            for (int mt = 0; mt < 2; mt++) {
                const int gm0 = bm + wm * 32 + mt * 16 + gid;
                stg_cs_f2(C + (size_t)gm0 * Vocab + gn,
                          acc[mt][nt][0] + bv[nt].x, acc[mt][nt][1] + bv[nt].y);
                stg_cs_f2(C + (size_t)(gm0 + 8) * Vocab + gn,
                          acc[mt][nt][2] + bv[nt].x, acc[mt][nt][3] + bv[nt].y);
            }
        }
        __syncthreads();   // all reads of this A buffer done before it is overwritten
    }
}

// ------------------------------------ launch --------------------------------------
extern "C" void kernel_launch(void* const* d_in, const int* in_sizes, int n_in,
                              void* d_out, int out_size)
{
    (void)in_sizes; (void)n_in; (void)out_size;
    const float* x     = (const float*)d_in[0];
    const float* W_ih0 = (const float*)d_in[1];
    const float* W_hh0 = (const float*)d_in[2];
    const float* b_ih0 = (const float*)d_in[3];
    const float* b_hh0 = (const float*)d_in[4];
    const float* W_ih1 = (const float*)d_in[5];
    const float* W_hh1 = (const float*)d_in[6];
    const float* b_ih1 = (const float*)d_in[7];
    const float* b_hh1 = (const float*)d_in[8];
    const float* Wl    = (const float*)d_in[9];
    const float* bl    = (const float*)d_in[10];
    float* out = (float*)d_out;

    void* p;
    cudaGetSymbolAddress(&p, g_xproj); float* xproj = (float*)p;
    cudaGetSymbolAddress(&p, g_h1);    float* h1    = (float*)p;
    cudaGetSymbolAddress(&p, g_Ahi);   __nv_bfloat16* Ahi = (__nv_bfloat16*)p;
    cudaGetSymbolAddress(&p, g_Alo);   __nv_bfloat16* Alo = (__nv_bfloat16*)p;
    cudaGetSymbolAddress(&p, g_Bhi);   __nv_bfloat16* Bhi = (__nv_bfloat16*)p;
    cudaGetSymbolAddress(&p, g_Blo);   __nv_bfloat16* Blo = (__nv_bfloat16*)p;

    // Wl split (independent of LSTM chain)
    cvt_split<<<(Vocab * Hdim + 255) / 256, 256>>>(Wl, Bhi, Blo, Vocab * Hdim);

    // Layer 0 input projection
    gemm_nt_bias<<<dim3(Gdim / 64, Mrows / 64), 256>>>(
        x, W_ih0, b_ih0, b_hh0, xproj, Mrows, Gdim, INSZ);
    // Layer 0 recurrence -> h1 (fp32)
    lstm_layer<<<Bsz, Gdim>>>(xproj, W_hh0, h1, nullptr, nullptr);
    // Layer 1 input projection
    gemm_nt_bias<<<dim3(Gdim / 64, Mrows / 64), 256>>>(
        h1, W_ih1, b_ih1, b_hh1, xproj, Mrows, Gdim, Hdim);
    // Layer 1 recurrence -> bf16 hi/lo split directly
    lstm_layer<<<Bsz, Gdim>>>(xproj, W_hh1, nullptr, Ahi, Alo);

    // Logits via pipelined HMMA bf16 3-pass split
    cudaFuncSetAttribute(logits_gemm, cudaFuncAttributeMaxDynamicSharedMemorySize, LG_SMEM);
    logits_gemm<<<dim3(Vocab / 64, Mrows / (NM_TILES * 128)), 256, LG_SMEM>>>(
        Ahi, Alo, Bhi, Blo, bl, out);
}